// round 11
// baseline (speedup 1.0000x reference)
#include <cuda_runtime.h>
#include <cstdint>

// Problem constants: B=512, T=256, C=384, HS=16
#define TT   256
#define CC   384
#define HSZ  16
#define KCH  32
#define NKC  (CC/KCH)    // 12
#define XP   36          // x buffer row stride (floats), conflict-free (proven R7)
#define QKP  20          // attn q/k row stride
#define VPD  20          // attn v row stride

// packed W scratch: [192 k-pairs][48 cols], hi + lo bf16x2 words (q-scale folded)
__device__ unsigned g_whu[192 * 48];
__device__ unsigned g_wlu[192 * 48];

// smem: phase1 x buffers 8 warps x 2 bufs x 32 rows x 36 = 18432 f = 73728 B (max)
//       phase2 union: q 5120 + k 5120 + v 5120 + psum 256 + rinv 32 = 15648 f
#define SMEM_FLOATS 18432
#define SMEM_BYTES  (SMEM_FLOATS * 4)

__device__ __forceinline__ unsigned f2tf(float f) {
    unsigned r;
    asm("cvt.rna.tf32.f32 %0, %1;" : "=r"(r) : "f"(f));
    return r;
}
__device__ __forceinline__ unsigned pk2(float lo, float hi) {
    unsigned r;
    asm("cvt.rn.bf16x2.f32 %0, %1, %2;" : "=r"(r) : "f"(hi), "f"(lo));
    return r;
}
__device__ __forceinline__ float bflo(unsigned u) { return __uint_as_float(u << 16); }
__device__ __forceinline__ float bfhi(unsigned u) { return __uint_as_float(u & 0xffff0000u); }
__device__ __forceinline__ unsigned pkres(float lo, float hi, unsigned h) {
    return pk2(lo - bflo(h), hi - bfhi(h));
}

__device__ __forceinline__ void mma_tf32(float* c, const unsigned* a, const unsigned* b) {
    asm volatile(
        "mma.sync.aligned.m16n8k8.row.col.f32.tf32.tf32.f32 "
        "{%0,%1,%2,%3}, {%4,%5,%6,%7}, {%8,%9}, {%0,%1,%2,%3};"
        : "+f"(c[0]), "+f"(c[1]), "+f"(c[2]), "+f"(c[3])
        : "r"(a[0]), "r"(a[1]), "r"(a[2]), "r"(a[3]), "r"(b[0]), "r"(b[1]));
}
__device__ __forceinline__ void mma_bf16(float* c, const unsigned* a, const unsigned* b) {
    asm volatile(
        "mma.sync.aligned.m16n8k16.row.col.f32.bf16.bf16.f32 "
        "{%0,%1,%2,%3}, {%4,%5,%6,%7}, {%8,%9}, {%0,%1,%2,%3};"
        : "+f"(c[0]), "+f"(c[1]), "+f"(c[2]), "+f"(c[3])
        : "r"(a[0]), "r"(a[1]), "r"(a[2]), "r"(a[3]), "r"(b[0]), "r"(b[1]));
}
__device__ __forceinline__ void cpa16(uint32_t saddr, const float* g) {
    asm volatile("cp.async.ca.shared.global [%0], [%1], 16;" :: "r"(saddr), "l"(g));
}

// ============== tiny pre-kernel: pack W (q-cols pre-scaled) into bf16 hi/lo ======
__global__ void pack_w_kernel(const float* __restrict__ wk,
                              const float* __restrict__ wq,
                              const float* __restrict__ wv)
{
    int f = blockIdx.x * 256 + threadIdx.x;      // 0..9215
    if (f >= 192 * 48) return;
    int kp = f / 48, c = f % 48;
    int gk = 2 * kp;
    const float* src = (c < 16) ? (wq + gk * HSZ + c)
                     : (c < 32) ? (wk + gk * HSZ + (c - 16))
                                : (wv + gk * HSZ + (c - 32));
    float s  = (c < 16) ? rsqrtf((float)CC) : 1.0f;
    float w0 = src[0]   * s;
    float w1 = src[HSZ] * s;
    unsigned h = pk2(w0, w1);
    g_whu[f] = h;
    g_wlu[f] = pkres(w0, w1, h);
}

// ====================== fused kernel: projection + attention ======================
__global__ void __launch_bounds__(256, 3) head_fused_kernel(
    const float* __restrict__ x,
    float* __restrict__ out)
{
    extern __shared__ float sm[];
    const int b    = blockIdx.x;
    const int tid  = threadIdx.x;
    const int lane = tid & 31;
    const int warp = tid >> 5;
    const int grp  = lane >> 2;  // 0..7
    const int tig  = lane & 3;   // 0..3

    const uint32_t sm_base = (uint32_t)__cvta_generic_to_shared(sm);

    // phase-2 smem views (overlap phase-1 x buffers; separated by barriers)
    float* q_s  = sm;
    float* k_s  = q_s + TT * QKP;
    float* v_s  = k_s + TT * QKP;
    float* psum = v_s + TT * VPD;
    float* rinv = psum + 8 * 32;

    const float* xb = x + (size_t)b * TT * CC;
    const int R = warp * 32;

    // ========= Phase 1: qkv = x @ Wpacked — BARRIER-FREE (x is warp-private) =====
    const int lbase = warp * 2 * 32 * XP;   // this warp's x double-buffer (floats)

    float acc[2][6][4];
#pragma unroll
    for (int mt = 0; mt < 2; ++mt)
#pragma unroll
        for (int nt = 0; nt < 6; ++nt)
#pragma unroll
            for (int e = 0; e < 4; ++e) acc[mt][nt][e] = 0.f;

    auto load_x = [&](int kc, int buf) {
        const float* xg = xb + kc * KCH;
        uint32_t base = sm_base + (uint32_t)(lbase + buf * 32 * XP) * 4u;
#pragma unroll
        for (int i = 0; i < 8; ++i) {
            int row = (lane >> 3) + i * 4;       // local row 0..31
            int c4  = (lane & 7) * 4;
            cpa16(base + (uint32_t)(row * XP + c4) * 4u, xg + (R + row) * CC + c4);
        }
    };

    load_x(0, 0);
    asm volatile("cp.async.commit_group;");

    for (int kc = 0; kc < NKC; ++kc) {
        const int buf = kc & 1;
        if (kc + 1 < NKC) {
            load_x(kc + 1, buf ^ 1);
            asm volatile("cp.async.commit_group;");
            asm volatile("cp.async.wait_group 1;");
        } else {
            asm volatile("cp.async.wait_group 0;");
        }
        // no __syncthreads: this warp reads only its own buffer

        const float* xs = sm + lbase + buf * 32 * XP;

#pragma unroll
        for (int ch = 0; ch < 2; ++ch) {
            const int ko = ch * 16;
            unsigned ah[2][4], al[2][4];
#pragma unroll
            for (int mt = 0; mt < 2; ++mt) {
                int r0 = mt * 16 + grp;          // local rows
                float2 x0 = *reinterpret_cast<const float2*>(xs + r0 * XP + ko + 2 * tig);
                float2 x1 = *reinterpret_cast<const float2*>(xs + (r0 + 8) * XP + ko + 2 * tig);
                float2 x2 = *reinterpret_cast<const float2*>(xs + r0 * XP + ko + 8 + 2 * tig);
                float2 x3 = *reinterpret_cast<const float2*>(xs + (r0 + 8) * XP + ko + 8 + 2 * tig);
                ah[mt][0] = pk2(x0.x, x0.y); al[mt][0] = pkres(x0.x, x0.y, ah[mt][0]);
                ah[mt][1] = pk2(x1.x, x1.y); al[mt][1] = pkres(x1.x, x1.y, ah[mt][1]);
                ah[mt][2] = pk2(x2.x, x2.y); al[mt][2] = pkres(x2.x, x2.y, ah[mt][2]);
                ah[mt][3] = pk2(x3.x, x3.y); al[mt][3] = pkres(x3.x, x3.y, ah[mt][3]);
            }
            const unsigned* whp = g_whu + (kc * 16 + ch * 8) * 48;
            const unsigned* wlp = g_wlu + (kc * 16 + ch * 8) * 48;
#pragma unroll
            for (int nt = 0; nt < 6; ++nt) {
                int cb = nt * 8 + grp;
                unsigned bh[2], bl[2];
                bh[0] = __ldg(whp + tig * 48 + cb);
                bh[1] = __ldg(whp + (4 + tig) * 48 + cb);
                bl[0] = __ldg(wlp + tig * 48 + cb);
                bl[1] = __ldg(wlp + (4 + tig) * 48 + cb);
#pragma unroll
                for (int mt = 0; mt < 2; ++mt) {
                    mma_bf16(acc[mt][nt], ah[mt], bh);
                    mma_bf16(acc[mt][nt], ah[mt], bl);
                    mma_bf16(acc[mt][nt], al[mt], bh);
                }
            }
        }
    }
    __syncthreads();   // all warps done with their x buffers before scatter clobbers

    // scatter qkv (q scale already folded into W); q/k pre-rounded tf32, v raw
#pragma unroll
    for (int mt = 0; mt < 2; ++mt)
#pragma unroll
        for (int nt = 0; nt < 6; ++nt)
#pragma unroll
            for (int e = 0; e < 4; ++e) {
                int r   = R + mt * 16 + grp + ((e >= 2) ? 8 : 0);
                int cgl = nt * 8 + 2 * tig + (e & 1);
                float v = acc[mt][nt][e];
                if (cgl < 16)      q_s[r * QKP + cgl]        = __uint_as_float(f2tf(v));
                else if (cgl < 32) k_s[r * QKP + (cgl - 16)] = __uint_as_float(f2tf(v));
                else               v_s[r * VPD + (cgl - 32)] = v;
            }
    __syncthreads();

    // ========= Phase 2: attention, column softmax, balanced triangle ==============
    const int rb0 = warp * 16;
    const int rb1 = 240 - warp * 16;
    int rb[2] = {rb0, rb1};

    float oacc[2][2][4];
#pragma unroll
    for (int mt = 0; mt < 2; ++mt)
#pragma unroll
        for (int nt = 0; nt < 2; ++nt)
#pragma unroll
            for (int e = 0; e < 4; ++e) oacc[mt][nt][e] = 0.f;

    for (int blk = 0; blk < TT / 32; ++blk) {
        const int s0 = blk * 32;
        const bool act0 = (warp >= 2 * blk);
        const bool act1 = ((15 - warp) >= 2 * blk);
        const bool anyact = act1;

        float ef[2][4][4];
#pragma unroll
        for (int mt = 0; mt < 2; ++mt)
#pragma unroll
            for (int nt = 0; nt < 4; ++nt)
#pragma unroll
                for (int e = 0; e < 4; ++e) ef[mt][nt][e] = 0.f;

        float ps[4][2];
#pragma unroll
        for (int nt = 0; nt < 4; ++nt) { ps[nt][0] = 0.f; ps[nt][1] = 0.f; }

        if (anyact) {
            // S = q k^T (K=16), tf32, operands pre-rounded
#pragma unroll
            for (int k8 = 0; k8 < 2; ++k8) {
                const int ko = k8 * 8;
                unsigned aq[2][4];
#pragma unroll
                for (int mt = 0; mt < 2; ++mt) {
                    if (mt == 0 && !act0) continue;
                    int r0 = rb[mt] + grp;
                    aq[mt][0] = __float_as_uint(q_s[r0 * QKP + ko + tig]);
                    aq[mt][1] = __float_as_uint(q_s[(r0 + 8) * QKP + ko + tig]);
                    aq[mt][2] = __float_as_uint(q_s[r0 * QKP + ko + tig + 4]);
                    aq[mt][3] = __float_as_uint(q_s[(r0 + 8) * QKP + ko + tig + 4]);
                }
#pragma unroll
                for (int nt = 0; nt < 4; ++nt) {
                    int sc = s0 + nt * 8 + grp;
                    unsigned bb[2];
                    bb[0] = __float_as_uint(k_s[sc * QKP + ko + tig]);
                    bb[1] = __float_as_uint(k_s[sc * QKP + ko + tig + 4]);
                    if (act0) mma_tf32(ef[0][nt], aq[0], bb);
                    mma_tf32(ef[1][nt], aq[1], bb);
                }
            }
            // mask + exp
#pragma unroll
            for (int mt = 0; mt < 2; ++mt) {
                if (mt == 0 && !act0) {
#pragma unroll
                    for (int nt = 0; nt < 4; ++nt)
#pragma unroll
                        for (int e = 0; e < 4; ++e) ef[0][nt][e] = 0.f;
                    continue;
                }
#pragma unroll
                for (int nt = 0; nt < 4; ++nt)
#pragma unroll
                    for (int e = 0; e < 4; ++e) {
                        int r  = rb[mt] + grp + ((e >= 2) ? 8 : 0);
                        int sg = s0 + nt * 8 + 2 * tig + (e & 1);
                        ef[mt][nt][e] = (sg <= r) ? __expf(ef[mt][nt][e]) : 0.f;
                    }
            }
            // per-column partial sums
#pragma unroll
            for (int nt = 0; nt < 4; ++nt)
#pragma unroll
                for (int bb2 = 0; bb2 < 2; ++bb2) {
                    float s = ef[0][nt][bb2] + ef[0][nt][bb2 + 2]
                            + ef[1][nt][bb2] + ef[1][nt][bb2 + 2];
                    s += __shfl_xor_sync(0xffffffffu, s, 4);
                    s += __shfl_xor_sync(0xffffffffu, s, 8);
                    s += __shfl_xor_sync(0xffffffffu, s, 16);
                    ps[nt][bb2] = s;
                }
        }
        if (grp == 0) {
#pragma unroll
            for (int nt = 0; nt < 4; ++nt) {
                psum[warp * 32 + nt * 8 + 2 * tig]     = ps[nt][0];
                psum[warp * 32 + nt * 8 + 2 * tig + 1] = ps[nt][1];
            }
        }
        __syncthreads();
        if (tid < 32) {
            float s = 0.f;
#pragma unroll
            for (int w = 0; w < 8; ++w) s += psum[w * 32 + tid];
            rinv[tid] = 1.0f / s;
        }
        __syncthreads();

        if (anyact) {
            // PV in bf16 3-term, k16 (C-frag == A-frag layout, no shuffles)
#pragma unroll
            for (int ch = 0; ch < 2; ++ch) {
                const int sb = s0 + ch * 16;
                unsigned pah[2][4], pal[2][4];
#pragma unroll
                for (int mt = 0; mt < 2; ++mt) {
                    if (mt == 0 && !act0) continue;
#pragma unroll
                    for (int hq = 0; hq < 2; ++hq) {
                        float e0 = ef[mt][2 * ch + hq][0];
                        float e1 = ef[mt][2 * ch + hq][1];
                        float e2 = ef[mt][2 * ch + hq][2];
                        float e3 = ef[mt][2 * ch + hq][3];
                        pah[mt][2 * hq]     = pk2(e0, e1);
                        pal[mt][2 * hq]     = pkres(e0, e1, pah[mt][2 * hq]);
                        pah[mt][2 * hq + 1] = pk2(e2, e3);
                        pal[mt][2 * hq + 1] = pkres(e2, e3, pah[mt][2 * hq + 1]);
                    }
                }
                float r0 = rinv[ch * 16 + 2 * tig];
                float r1 = rinv[ch * 16 + 2 * tig + 1];
                float r2 = rinv[ch * 16 + 8 + 2 * tig];
                float r3 = rinv[ch * 16 + 9 + 2 * tig];
#pragma unroll
                for (int nt = 0; nt < 2; ++nt) {
                    int d = nt * 8 + grp;
                    float b0 = v_s[(sb + 2 * tig)     * VPD + d] * r0;
                    float b1 = v_s[(sb + 2 * tig + 1) * VPD + d] * r1;
                    float b2 = v_s[(sb + 8 + 2 * tig) * VPD + d] * r2;
                    float b3 = v_s[(sb + 9 + 2 * tig) * VPD + d] * r3;
                    unsigned bh[2], bl[2];
                    bh[0] = pk2(b0, b1); bl[0] = pkres(b0, b1, bh[0]);
                    bh[1] = pk2(b2, b3); bl[1] = pkres(b2, b3, bh[1]);
                    if (act0) {
                        mma_bf16(oacc[0][nt], pah[0], bh);
                        mma_bf16(oacc[0][nt], pah[0], bl);
                        mma_bf16(oacc[0][nt], pal[0], bh);
                    }
                    mma_bf16(oacc[1][nt], pah[1], bh);
                    mma_bf16(oacc[1][nt], pah[1], bl);
                    mma_bf16(oacc[1][nt], pal[1], bh);
                }
            }
        }
    }

    float* ob = out + (size_t)b * TT * HSZ;
#pragma unroll
    for (int mt = 0; mt < 2; ++mt)
#pragma unroll
        for (int nt = 0; nt < 2; ++nt) {
            int r0 = rb[mt] + grp;
            int c  = nt * 8 + 2 * tig;
            *reinterpret_cast<float2*>(ob + r0 * HSZ + c) =
                make_float2(oacc[mt][nt][0], oacc[mt][nt][1]);
            *reinterpret_cast<float2*>(ob + (r0 + 8) * HSZ + c) =
                make_float2(oacc[mt][nt][2], oacc[mt][nt][3]);
        }
}

extern "C" void kernel_launch(void* const* d_in, const int* in_sizes, int n_in,
                              void* d_out, int out_size) {
    const float* x  = (const float*)d_in[0];
    const float* wk = (const float*)d_in[1];
    const float* wq = (const float*)d_in[2];
    const float* wv = (const float*)d_in[3];
    float* out      = (float*)d_out;

    const int B = in_sizes[0] / (TT * CC);  // 512

    cudaFuncSetAttribute(head_fused_kernel,
                         cudaFuncAttributeMaxDynamicSharedMemorySize, SMEM_BYTES);

    pack_w_kernel<<<36, 256>>>(wk, wq, wv);
    head_fused_kernel<<<B, 256, SMEM_BYTES>>>(x, out);
}

// round 12
// speedup vs baseline: 2.1016x; 2.1016x over previous
#include <cuda_runtime.h>
#include <cstdint>

// Problem constants: B=512, T=256, C=384, HS=16
#define TT   256
#define CC   384
#define HSZ  16
#define KCH  32          // K-chunk for projection
#define NKC  (CC/KCH)    // 12
#define XP1  36          // x tile row stride (floats), conflict-free (proven R7)
#define WSP  56          // W packed tile row stride (words), conflict-free (proven R7)
#define QKP  20          // q/k row stride
#define VPD  28          // v row stride (proven R7)

// packed W: [192 k-pairs][48 cols] bf16x2 hi/lo words, q-cols pre-scaled
__device__ unsigned g_whu[192 * 48];
__device__ unsigned g_wlu[192 * 48];

// smem (floats/words):
//  phase1: 2 x (256*36 + 2*16*56) = 22016 = 88064 B  (max)
//  phase2: q[256*20] k[256*20] v[256*28] psum[2*256] = 17920
#define SMEM_FLOATS (2 * (TT * XP1 + 2 * 16 * WSP))
#define SMEM_BYTES  (SMEM_FLOATS * 4)

__device__ __forceinline__ unsigned f2tf(float f) {
    unsigned r;
    asm("cvt.rna.tf32.f32 %0, %1;" : "=r"(r) : "f"(f));
    return r;
}
__device__ __forceinline__ unsigned pk2(float lo, float hi) {
    unsigned r;
    asm("cvt.rn.bf16x2.f32 %0, %1, %2;" : "=r"(r) : "f"(hi), "f"(lo));
    return r;
}
__device__ __forceinline__ float bflo(unsigned u) { return __uint_as_float(u << 16); }
__device__ __forceinline__ float bfhi(unsigned u) { return __uint_as_float(u & 0xffff0000u); }
__device__ __forceinline__ unsigned pkres(float lo, float hi, unsigned h) {
    return pk2(lo - bflo(h), hi - bfhi(h));
}

__device__ __forceinline__ void mma_tf32(float* c, const unsigned* a, const unsigned* b) {
    asm volatile(
        "mma.sync.aligned.m16n8k8.row.col.f32.tf32.tf32.f32 "
        "{%0,%1,%2,%3}, {%4,%5,%6,%7}, {%8,%9}, {%0,%1,%2,%3};"
        : "+f"(c[0]), "+f"(c[1]), "+f"(c[2]), "+f"(c[3])
        : "r"(a[0]), "r"(a[1]), "r"(a[2]), "r"(a[3]), "r"(b[0]), "r"(b[1]));
}
__device__ __forceinline__ void mma_bf16(float* c, const unsigned* a, const unsigned* b) {
    asm volatile(
        "mma.sync.aligned.m16n8k16.row.col.f32.bf16.bf16.f32 "
        "{%0,%1,%2,%3}, {%4,%5,%6,%7}, {%8,%9}, {%0,%1,%2,%3};"
        : "+f"(c[0]), "+f"(c[1]), "+f"(c[2]), "+f"(c[3])
        : "r"(a[0]), "r"(a[1]), "r"(a[2]), "r"(a[3]), "r"(b[0]), "r"(b[1]));
}
__device__ __forceinline__ void cpa16(uint32_t saddr, const void* g) {
    asm volatile("cp.async.ca.shared.global [%0], [%1], 16;" :: "r"(saddr), "l"(g));
}

// ============== pre-kernel: pack W (q-cols pre-scaled) into bf16 hi/lo ===========
__global__ void pack_w_kernel(const float* __restrict__ wk,
                              const float* __restrict__ wq,
                              const float* __restrict__ wv)
{
    int f = blockIdx.x * 256 + threadIdx.x;      // 0..9215
    if (f >= 192 * 48) return;
    int kp = f / 48, c = f % 48;
    int gk = 2 * kp;
    const float* src = (c < 16) ? (wq + gk * HSZ + c)
                     : (c < 32) ? (wk + gk * HSZ + (c - 16))
                                : (wv + gk * HSZ + (c - 32));
    float s  = (c < 16) ? rsqrtf((float)CC) : 1.0f;
    float w0 = src[0]   * s;
    float w1 = src[HSZ] * s;
    unsigned h = pk2(w0, w1);
    g_whu[f] = h;
    g_wlu[f] = pkres(w0, w1, h);
}

// ====================== fused kernel: projection + attention ======================
__global__ void __launch_bounds__(256, 2) head_fused_kernel(
    const float* __restrict__ x,
    float* __restrict__ out)
{
    extern __shared__ float sm[];
    const int b    = blockIdx.x;
    const int tid  = threadIdx.x;
    const int lane = tid & 31;
    const int warp = tid >> 5;
    const int grp  = lane >> 2;  // 0..7
    const int tig  = lane & 3;   // 0..3

    const uint32_t sm_base = (uint32_t)__cvta_generic_to_shared(sm);

    // phase-2 smem views
    float* q_s  = sm;
    float* k_s  = q_s + TT * QKP;
    float* v_s  = k_s + TT * QKP;
    float* psum = v_s + TT * VPD;     // [2][256] parity-buffered

    const float* xb = x + (size_t)b * TT * CC;
    const int R = warp * 32;

    // ============ Phase 1: qkv = x @ Wpacked, bf16 3-term, cp.async DB ============
    float acc[2][6][4];
#pragma unroll
    for (int mt = 0; mt < 2; ++mt)
#pragma unroll
        for (int nt = 0; nt < 6; ++nt)
#pragma unroll
            for (int e = 0; e < 4; ++e) acc[mt][nt][e] = 0.f;

    auto load_chunk = [&](int kc, int buf) {
        const float* xg = xb + kc * KCH;
        uint32_t xs_a = sm_base + (uint32_t)(buf * TT * XP1) * 4u;
#pragma unroll
        for (int i = 0; i < 8; ++i) {
            int row = (tid >> 3) + i * 32;
            int c4  = (tid & 7) * 4;
            cpa16(xs_a + (uint32_t)(row * XP1 + c4) * 4u, xg + row * CC + c4);
        }
        // W: cp.async pre-packed hi/lo words into stride-56 smem rows
        const uint32_t wbase = (uint32_t)(2 * TT * XP1 + buf * 2 * 16 * WSP);
#pragma unroll
        for (int i = 0; i < 2; ++i) {
            int f = tid + i * 256;                  // need 384 transfers of 16B
            if (f < 384) {
                int isLo = (f >= 192);
                int g2   = f - isLo * 192;
                int kp   = g2 / 12;
                int c4   = (g2 % 12) * 4;
                const unsigned* src = (isLo ? g_wlu : g_whu) + (kc * 16 + kp) * 48 + c4;
                uint32_t dst = sm_base +
                    (wbase + (uint32_t)(isLo * 16 * WSP + kp * WSP + c4)) * 4u;
                cpa16(dst, src);
            }
        }
    };

    load_chunk(0, 0);
    asm volatile("cp.async.commit_group;");

    for (int kc = 0; kc < NKC; ++kc) {
        const int buf = kc & 1;
        if (kc + 1 < NKC) {
            load_chunk(kc + 1, buf ^ 1);
            asm volatile("cp.async.commit_group;");
            asm volatile("cp.async.wait_group 1;");
        } else {
            asm volatile("cp.async.wait_group 0;");
        }
        __syncthreads();

        const float* xs = sm + buf * TT * XP1;
        const unsigned* wh = reinterpret_cast<const unsigned*>(
            sm + 2 * TT * XP1 + buf * 2 * 16 * WSP);
        const unsigned* wl = wh + 16 * WSP;

#pragma unroll
        for (int ch = 0; ch < 2; ++ch) {          // two k16 chunks per kc
            const int ko = ch * 16;
            unsigned ah[2][4], al[2][4];
#pragma unroll
            for (int mt = 0; mt < 2; ++mt) {
                int r0 = R + mt * 16 + grp;
                float2 x0 = *reinterpret_cast<const float2*>(xs + r0 * XP1 + ko + 2 * tig);
                float2 x1 = *reinterpret_cast<const float2*>(xs + (r0 + 8) * XP1 + ko + 2 * tig);
                float2 x2 = *reinterpret_cast<const float2*>(xs + r0 * XP1 + ko + 8 + 2 * tig);
                float2 x3 = *reinterpret_cast<const float2*>(xs + (r0 + 8) * XP1 + ko + 8 + 2 * tig);
                ah[mt][0] = pk2(x0.x, x0.y); al[mt][0] = pkres(x0.x, x0.y, ah[mt][0]);
                ah[mt][1] = pk2(x1.x, x1.y); al[mt][1] = pkres(x1.x, x1.y, ah[mt][1]);
                ah[mt][2] = pk2(x2.x, x2.y); al[mt][2] = pkres(x2.x, x2.y, ah[mt][2]);
                ah[mt][3] = pk2(x3.x, x3.y); al[mt][3] = pkres(x3.x, x3.y, ah[mt][3]);
            }
#pragma unroll
            for (int nt = 0; nt < 6; ++nt) {
                int cb = nt * 8 + grp;
                unsigned bh[2], bl[2];
                bh[0] = wh[(ch * 8 + tig) * WSP + cb];
                bh[1] = wh[(ch * 8 + 4 + tig) * WSP + cb];
                bl[0] = wl[(ch * 8 + tig) * WSP + cb];
                bl[1] = wl[(ch * 8 + 4 + tig) * WSP + cb];
#pragma unroll
                for (int mt = 0; mt < 2; ++mt) {
                    mma_bf16(acc[mt][nt], ah[mt], bh);
                    mma_bf16(acc[mt][nt], ah[mt], bl);
                    mma_bf16(acc[mt][nt], al[mt], bh);
                }
            }
        }
        __syncthreads();
    }

    // scatter qkv; q scale pre-folded into W; q/k pre-rounded tf32, v raw fp32
#pragma unroll
    for (int mt = 0; mt < 2; ++mt)
#pragma unroll
        for (int nt = 0; nt < 6; ++nt)
#pragma unroll
            for (int e = 0; e < 4; ++e) {
                int r   = R + mt * 16 + grp + ((e >= 2) ? 8 : 0);
                int cgl = nt * 8 + 2 * tig + (e & 1);
                float v = acc[mt][nt][e];
                if (cgl < 16)      q_s[r * QKP + cgl]        = __uint_as_float(f2tf(v));
                else if (cgl < 32) k_s[r * QKP + (cgl - 16)] = __uint_as_float(f2tf(v));
                else               v_s[r * VPD + (cgl - 32)] = v;
            }
    __syncthreads();

    // ========= Phase 2: attention, column softmax, single barrier per block =======
    const int rb0 = warp * 16;
    const int rb1 = 240 - warp * 16;
    int rb[2] = {rb0, rb1};

    float oacc[2][2][4];
#pragma unroll
    for (int mt = 0; mt < 2; ++mt)
#pragma unroll
        for (int nt = 0; nt < 2; ++nt)
#pragma unroll
            for (int e = 0; e < 4; ++e) oacc[mt][nt][e] = 0.f;

    for (int blk = 0; blk < TT / 32; ++blk) {
        const int s0 = blk * 32;
        const bool act0 = (warp >= 2 * blk);
        const bool act1 = ((15 - warp) >= 2 * blk);
        const bool anyact = act1;
        float* psumP = psum + (blk & 1) * 256;

        float ef[2][4][4];
#pragma unroll
        for (int mt = 0; mt < 2; ++mt)
#pragma unroll
            for (int nt = 0; nt < 4; ++nt)
#pragma unroll
                for (int e = 0; e < 4; ++e) ef[mt][nt][e] = 0.f;

        float ps[4][2];
#pragma unroll
        for (int nt = 0; nt < 4; ++nt) { ps[nt][0] = 0.f; ps[nt][1] = 0.f; }

        if (anyact) {
            // S = q k^T (K=16), tf32, operands pre-rounded
#pragma unroll
            for (int k8 = 0; k8 < 2; ++k8) {
                const int ko = k8 * 8;
                unsigned aq[2][4];
#pragma unroll
                for (int mt = 0; mt < 2; ++mt) {
                    if (mt == 0 && !act0) continue;
                    int r0 = rb[mt] + grp;
                    aq[mt][0] = __float_as_uint(q_s[r0 * QKP + ko + tig]);
                    aq[mt][1] = __float_as_uint(q_s[(r0 + 8) * QKP + ko + tig]);
                    aq[mt][2] = __float_as_uint(q_s[r0 * QKP + ko + tig + 4]);
                    aq[mt][3] = __float_as_uint(q_s[(r0 + 8) * QKP + ko + tig + 4]);
                }
#pragma unroll
                for (int nt = 0; nt < 4; ++nt) {
                    int sc = s0 + nt * 8 + grp;
                    unsigned bb[2];
                    bb[0] = __float_as_uint(k_s[sc * QKP + ko + tig]);
                    bb[1] = __float_as_uint(k_s[sc * QKP + ko + tig + 4]);
                    if (act0) mma_tf32(ef[0][nt], aq[0], bb);
                    mma_tf32(ef[1][nt], aq[1], bb);
                }
            }
            // mask + exp
#pragma unroll
            for (int mt = 0; mt < 2; ++mt) {
                if (mt == 0 && !act0) {
#pragma unroll
                    for (int nt = 0; nt < 4; ++nt)
#pragma unroll
                        for (int e = 0; e < 4; ++e) ef[0][nt][e] = 0.f;
                    continue;
                }
#pragma unroll
                for (int nt = 0; nt < 4; ++nt)
#pragma unroll
                    for (int e = 0; e < 4; ++e) {
                        int r  = rb[mt] + grp + ((e >= 2) ? 8 : 0);
                        int sg = s0 + nt * 8 + 2 * tig + (e & 1);
                        ef[mt][nt][e] = (sg <= r) ? __expf(ef[mt][nt][e]) : 0.f;
                    }
            }
            // per-column partial sums over this warp's 32 rows
#pragma unroll
            for (int nt = 0; nt < 4; ++nt)
#pragma unroll
                for (int bb2 = 0; bb2 < 2; ++bb2) {
                    float s = ef[0][nt][bb2] + ef[0][nt][bb2 + 2]
                            + ef[1][nt][bb2] + ef[1][nt][bb2 + 2];
                    s += __shfl_xor_sync(0xffffffffu, s, 4);
                    s += __shfl_xor_sync(0xffffffffu, s, 8);
                    s += __shfl_xor_sync(0xffffffffu, s, 16);
                    ps[nt][bb2] = s;
                }
        }
        if (grp == 0) {
#pragma unroll
            for (int nt = 0; nt < 4; ++nt) {
                psumP[warp * 32 + nt * 8 + 2 * tig]     = ps[nt][0];
                psumP[warp * 32 + nt * 8 + 2 * tig + 1] = ps[nt][1];
            }
        }
        __syncthreads();   // single barrier per block (parity buffer handles WAR)

        // every warp reduces its own rinv: lane L -> 1/denom of column s0+L
        float rv;
        {
            float tot = 0.f;
#pragma unroll
            for (int w = 0; w < 8; ++w) tot += psumP[w * 32 + lane];
            rv = 1.0f / tot;
        }

        if (anyact) {
            // PV in bf16 3-term, k16 (C-frag == A-frag layout, no P shuffles)
#pragma unroll
            for (int ch = 0; ch < 2; ++ch) {
                const int sb = s0 + ch * 16;
                unsigned pah[2][4], pal[2][4];
#pragma unroll
                for (int mt = 0; mt < 2; ++mt) {
                    if (mt == 0 && !act0) continue;
#pragma unroll
                    for (int hq = 0; hq < 2; ++hq) {
                        float e0 = ef[mt][2 * ch + hq][0];
                        float e1 = ef[mt][2 * ch + hq][1];
                        float e2 = ef[mt][2 * ch + hq][2];
                        float e3 = ef[mt][2 * ch + hq][3];
                        pah[mt][2 * hq]     = pk2(e0, e1);
                        pal[mt][2 * hq]     = pkres(e0, e1, pah[mt][2 * hq]);
                        pah[mt][2 * hq + 1] = pk2(e2, e3);
                        pal[mt][2 * hq + 1] = pkres(e2, e3, pah[mt][2 * hq + 1]);
                    }
                }
                float r0 = __shfl_sync(0xffffffffu, rv, ch * 16 + 2 * tig);
                float r1 = __shfl_sync(0xffffffffu, rv, ch * 16 + 2 * tig + 1);
                float r2 = __shfl_sync(0xffffffffu, rv, ch * 16 + 8 + 2 * tig);
                float r3 = __shfl_sync(0xffffffffu, rv, ch * 16 + 9 + 2 * tig);
#pragma unroll
                for (int nt = 0; nt < 2; ++nt) {
                    int d = nt * 8 + grp;
                    float b0 = v_s[(sb + 2 * tig)     * VPD + d] * r0;
                    float b1 = v_s[(sb + 2 * tig + 1) * VPD + d] * r1;
                    float b2 = v_s[(sb + 8 + 2 * tig) * VPD + d] * r2;
                    float b3 = v_s[(sb + 9 + 2 * tig) * VPD + d] * r3;
                    unsigned bh[2], bl[2];
                    bh[0] = pk2(b0, b1); bl[0] = pkres(b0, b1, bh[0]);
                    bh[1] = pk2(b2, b3); bl[1] = pkres(b2, b3, bh[1]);
                    if (act0) {
                        mma_bf16(oacc[0][nt], pah[0], bh);
                        mma_bf16(oacc[0][nt], pah[0], bl);
                        mma_bf16(oacc[0][nt], pal[0], bh);
                    }
                    mma_bf16(oacc[1][nt], pah[1], bh);
                    mma_bf16(oacc[1][nt], pah[1], bl);
                    mma_bf16(oacc[1][nt], pal[1], bh);
                }
            }
        }
    }

    float* ob = out + (size_t)b * TT * HSZ;
#pragma unroll
    for (int mt = 0; mt < 2; ++mt)
#pragma unroll
        for (int nt = 0; nt < 2; ++nt) {
            int r0 = rb[mt] + grp;
            int c  = nt * 8 + 2 * tig;
            *reinterpret_cast<float2*>(ob + r0 * HSZ + c) =
                make_float2(oacc[mt][nt][0], oacc[mt][nt][1]);
            *reinterpret_cast<float2*>(ob + (r0 + 8) * HSZ + c) =
                make_float2(oacc[mt][nt][2], oacc[mt][nt][3]);
        }
}

extern "C" void kernel_launch(void* const* d_in, const int* in_sizes, int n_in,
                              void* d_out, int out_size) {
    const float* x  = (const float*)d_in[0];
    const float* wk = (const float*)d_in[1];
    const float* wq = (const float*)d_in[2];
    const float* wv = (const float*)d_in[3];
    float* out      = (float*)d_out;

    const int B = in_sizes[0] / (TT * CC);  // 512

    cudaFuncSetAttribute(head_fused_kernel,
                         cudaFuncAttributeMaxDynamicSharedMemorySize, SMEM_BYTES);

    pack_w_kernel<<<36, 256>>>(wk, wq, wv);
    head_fused_kernel<<<B, 256, SMEM_BYTES>>>(x, out);
}

// round 13
// speedup vs baseline: 2.2638x; 1.0772x over previous
#include <cuda_runtime.h>
#include <cstdint>

// Problem constants: B=512, T=256, C=384, HS=16
#define TT   256
#define CC   384
#define HSZ  16
#define KCH  32          // K-chunk for projection
#define NKC  (CC/KCH)    // 12
#define XP1  36          // x tile row stride (floats), conflict-free (proven)
#define QKP  20          // q/k row stride
#define VPD  28          // v row stride (proven)

// packed W: 24 k16-chunks x 48 cb x 4 tig, uint4 = {bh0, bh1, bl0, bl1}
// (exact B-fragment payload; q-columns pre-scaled by C^-0.5)
__device__ uint4 g_w4[24 * 192];

// smem (floats):
//  phase1: x 2*256*36 = 18432 + W4 2*384 uint4 = 3072 words -> 21504 f = 86016 B (max)
//  phase2: q[256*20] k[256*20] v[256*28] psum[2*256] = 17920 f
#define SMEM_FLOATS (2 * TT * XP1 + 2 * 384 * 4)
#define SMEM_BYTES  (SMEM_FLOATS * 4)

__device__ __forceinline__ unsigned f2tf(float f) {
    unsigned r;
    asm("cvt.rna.tf32.f32 %0, %1;" : "=r"(r) : "f"(f));
    return r;
}
__device__ __forceinline__ unsigned pk2(float lo, float hi) {
    unsigned r;
    asm("cvt.rn.bf16x2.f32 %0, %1, %2;" : "=r"(r) : "f"(hi), "f"(lo));
    return r;
}
__device__ __forceinline__ float bflo(unsigned u) { return __uint_as_float(u << 16); }
__device__ __forceinline__ float bfhi(unsigned u) { return __uint_as_float(u & 0xffff0000u); }
__device__ __forceinline__ unsigned pkres(float lo, float hi, unsigned h) {
    return pk2(lo - bflo(h), hi - bfhi(h));
}

__device__ __forceinline__ void mma_tf32(float* c, const unsigned* a, const unsigned* b) {
    asm volatile(
        "mma.sync.aligned.m16n8k8.row.col.f32.tf32.tf32.f32 "
        "{%0,%1,%2,%3}, {%4,%5,%6,%7}, {%8,%9}, {%0,%1,%2,%3};"
        : "+f"(c[0]), "+f"(c[1]), "+f"(c[2]), "+f"(c[3])
        : "r"(a[0]), "r"(a[1]), "r"(a[2]), "r"(a[3]), "r"(b[0]), "r"(b[1]));
}
__device__ __forceinline__ void mma_bf16(float* c, const unsigned* a, const unsigned* b) {
    asm volatile(
        "mma.sync.aligned.m16n8k16.row.col.f32.bf16.bf16.f32 "
        "{%0,%1,%2,%3}, {%4,%5,%6,%7}, {%8,%9}, {%0,%1,%2,%3};"
        : "+f"(c[0]), "+f"(c[1]), "+f"(c[2]), "+f"(c[3])
        : "r"(a[0]), "r"(a[1]), "r"(a[2]), "r"(a[3]), "r"(b[0]), "r"(b[1]));
}
__device__ __forceinline__ void cpa16(uint32_t saddr, const void* g) {
    asm volatile("cp.async.ca.shared.global [%0], [%1], 16;" :: "r"(saddr), "l"(g));
}

// ===== pre-kernel: pack W into B-fragment uint4 layout (q-cols pre-scaled) =======
// f = (chunk*48 + cb)*4 + tig ; chunk = k16-chunk (0..23)
// uint4 = { pk2(w[kA],w[kA+1]), pk2(w[kB],w[kB+1]), residuals... }
// kA = chunk*16 + 2*tig ; kB = kA + 8   (matches bf16 B-fragment k mapping)
__global__ void pack_w_kernel(const float* __restrict__ wk,
                              const float* __restrict__ wq,
                              const float* __restrict__ wv)
{
    int f = blockIdx.x * 256 + threadIdx.x;      // 0..4607
    if (f >= 24 * 192) return;
    int chunk = f / 192;
    int rem   = f % 192;
    int cb    = rem / 4;
    int tg    = rem % 4;

    const float* w;
    int c;
    float s = 1.0f;
    if (cb < 16)      { w = wq; c = cb;      s = rsqrtf((float)CC); }
    else if (cb < 32) { w = wk; c = cb - 16; }
    else              { w = wv; c = cb - 32; }

    int kA = chunk * 16 + 2 * tg;
    int kB = kA + 8;
    float a0 = w[kA * HSZ + c] * s;
    float a1 = w[(kA + 1) * HSZ + c] * s;
    float b0 = w[kB * HSZ + c] * s;
    float b1 = w[(kB + 1) * HSZ + c] * s;
    unsigned h0 = pk2(a0, a1);
    unsigned h1 = pk2(b0, b1);
    uint4 r;
    r.x = h0;
    r.y = h1;
    r.z = pkres(a0, a1, h0);
    r.w = pkres(b0, b1, h1);
    g_w4[f] = r;
}

// ====================== fused kernel: projection + attention ======================
__global__ void __launch_bounds__(256, 2) head_fused_kernel(
    const float* __restrict__ x,
    float* __restrict__ out)
{
    extern __shared__ float sm[];
    const int b    = blockIdx.x;
    const int tid  = threadIdx.x;
    const int lane = tid & 31;
    const int warp = tid >> 5;
    const int grp  = lane >> 2;  // 0..7
    const int tig  = lane & 3;   // 0..3

    const uint32_t sm_base = (uint32_t)__cvta_generic_to_shared(sm);

    // phase-2 smem views (overlap phase-1 region)
    float* q_s  = sm;
    float* k_s  = q_s + TT * QKP;
    float* v_s  = k_s + TT * QKP;
    float* psum = v_s + TT * VPD;     // [2][256] parity-buffered

    const float* xb = x + (size_t)b * TT * CC;
    const int R = warp * 32;

    // ======= Phase 1: qkv = x @ Wpacked, bf16 3-term, one barrier per kc =========
    float acc[2][6][4];
#pragma unroll
    for (int mt = 0; mt < 2; ++mt)
#pragma unroll
        for (int nt = 0; nt < 6; ++nt)
#pragma unroll
            for (int e = 0; e < 4; ++e) acc[mt][nt][e] = 0.f;

    const uint32_t wsm_off = (uint32_t)(2 * TT * XP1) * 4u;   // byte offset of W4 region

    auto load_chunk = [&](int kc, int buf) {
        const float* xg = xb + kc * KCH;
        uint32_t xs_a = sm_base + (uint32_t)(buf * TT * XP1) * 4u;
#pragma unroll
        for (int i = 0; i < 8; ++i) {
            int row = (tid >> 3) + i * 32;
            int c4  = (tid & 7) * 4;
            cpa16(xs_a + (uint32_t)(row * XP1 + c4) * 4u, xg + row * CC + c4);
        }
        // W: linear copy of 384 uint4 (2 chunks) into this buffer
        const uint4* srcW = g_w4 + kc * 384;
        uint32_t wdst = sm_base + wsm_off + (uint32_t)buf * 384u * 16u;
#pragma unroll
        for (int i = 0; i < 2; ++i) {
            int f = tid + i * 256;
            if (f < 384) cpa16(wdst + (uint32_t)f * 16u, srcW + f);
        }
    };

    load_chunk(0, 0);
    asm volatile("cp.async.commit_group;");

    for (int kc = 0; kc < NKC; ++kc) {
        const int buf = kc & 1;
        asm volatile("cp.async.wait_group 0;");
        __syncthreads();   // load kc visible to all; prev compute done with buf^1
        if (kc + 1 < NKC) {
            load_chunk(kc + 1, buf ^ 1);
            asm volatile("cp.async.commit_group;");
        }

        const float* xs = sm + buf * TT * XP1;
        const uint4* w4 = reinterpret_cast<const uint4*>(sm + 2 * TT * XP1) + buf * 384;

#pragma unroll
        for (int ch = 0; ch < 2; ++ch) {          // two k16 chunks per kc
            const int ko = ch * 16;
            unsigned ah[2][4], al[2][4];
#pragma unroll
            for (int mt = 0; mt < 2; ++mt) {
                int r0 = R + mt * 16 + grp;
                float2 x0 = *reinterpret_cast<const float2*>(xs + r0 * XP1 + ko + 2 * tig);
                float2 x1 = *reinterpret_cast<const float2*>(xs + (r0 + 8) * XP1 + ko + 2 * tig);
                float2 x2 = *reinterpret_cast<const float2*>(xs + r0 * XP1 + ko + 8 + 2 * tig);
                float2 x3 = *reinterpret_cast<const float2*>(xs + (r0 + 8) * XP1 + ko + 8 + 2 * tig);
                ah[mt][0] = pk2(x0.x, x0.y); al[mt][0] = pkres(x0.x, x0.y, ah[mt][0]);
                ah[mt][1] = pk2(x1.x, x1.y); al[mt][1] = pkres(x1.x, x1.y, ah[mt][1]);
                ah[mt][2] = pk2(x2.x, x2.y); al[mt][2] = pkres(x2.x, x2.y, ah[mt][2]);
                ah[mt][3] = pk2(x3.x, x3.y); al[mt][3] = pkres(x3.x, x3.y, ah[mt][3]);
            }
            const uint4* wc = w4 + ch * 192;
#pragma unroll
            for (int nt = 0; nt < 6; ++nt) {
                uint4 q4 = wc[nt * 32 + lane];     // one LDS.128, conflict-free
                unsigned bh[2] = {q4.x, q4.y};
                unsigned bl[2] = {q4.z, q4.w};
#pragma unroll
                for (int mt = 0; mt < 2; ++mt) {
                    mma_bf16(acc[mt][nt], ah[mt], bh);
                    mma_bf16(acc[mt][nt], ah[mt], bl);
                    mma_bf16(acc[mt][nt], al[mt], bh);
                }
            }
        }
    }
    __syncthreads();   // all warps done reading x buffers before scatter clobbers

    // scatter qkv; q scale pre-folded into W; q/k pre-rounded tf32, v raw fp32
#pragma unroll
    for (int mt = 0; mt < 2; ++mt)
#pragma unroll
        for (int nt = 0; nt < 6; ++nt)
#pragma unroll
            for (int e = 0; e < 4; ++e) {
                int r   = R + mt * 16 + grp + ((e >= 2) ? 8 : 0);
                int cgl = nt * 8 + 2 * tig + (e & 1);
                float v = acc[mt][nt][e];
                if (cgl < 16)      q_s[r * QKP + cgl]        = __uint_as_float(f2tf(v));
                else if (cgl < 32) k_s[r * QKP + (cgl - 16)] = __uint_as_float(f2tf(v));
                else               v_s[r * VPD + (cgl - 32)] = v;
            }
    __syncthreads();

    // ========= Phase 2: attention, column softmax, single barrier per block =======
    const int rb0 = warp * 16;
    const int rb1 = 240 - warp * 16;
    int rb[2] = {rb0, rb1};

    float oacc[2][2][4];
#pragma unroll
    for (int mt = 0; mt < 2; ++mt)
#pragma unroll
        for (int nt = 0; nt < 2; ++nt)
#pragma unroll
            for (int e = 0; e < 4; ++e) oacc[mt][nt][e] = 0.f;

    for (int blk = 0; blk < TT / 32; ++blk) {
        const int s0 = blk * 32;
        const bool act0 = (warp >= 2 * blk);
        const bool act1 = ((15 - warp) >= 2 * blk);
        const bool anyact = act1;
        float* psumP = psum + (blk & 1) * 256;

        float ef[2][4][4];
#pragma unroll
        for (int mt = 0; mt < 2; ++mt)
#pragma unroll
            for (int nt = 0; nt < 4; ++nt)
#pragma unroll
                for (int e = 0; e < 4; ++e) ef[mt][nt][e] = 0.f;

        float ps[4][2];
#pragma unroll
        for (int nt = 0; nt < 4; ++nt) { ps[nt][0] = 0.f; ps[nt][1] = 0.f; }

        if (anyact) {
            // S = q k^T (K=16), tf32, operands pre-rounded
#pragma unroll
            for (int k8 = 0; k8 < 2; ++k8) {
                const int ko = k8 * 8;
                unsigned aq[2][4];
#pragma unroll
                for (int mt = 0; mt < 2; ++mt) {
                    if (mt == 0 && !act0) continue;
                    int r0 = rb[mt] + grp;
                    aq[mt][0] = __float_as_uint(q_s[r0 * QKP + ko + tig]);
                    aq[mt][1] = __float_as_uint(q_s[(r0 + 8) * QKP + ko + tig]);
                    aq[mt][2] = __float_as_uint(q_s[r0 * QKP + ko + tig + 4]);
                    aq[mt][3] = __float_as_uint(q_s[(r0 + 8) * QKP + ko + tig + 4]);
                }
#pragma unroll
                for (int nt = 0; nt < 4; ++nt) {
                    int sc = s0 + nt * 8 + grp;
                    unsigned bb[2];
                    bb[0] = __float_as_uint(k_s[sc * QKP + ko + tig]);
                    bb[1] = __float_as_uint(k_s[sc * QKP + ko + tig + 4]);
                    if (act0) mma_tf32(ef[0][nt], aq[0], bb);
                    mma_tf32(ef[1][nt], aq[1], bb);
                }
            }
            // mask + exp
#pragma unroll
            for (int mt = 0; mt < 2; ++mt) {
                if (mt == 0 && !act0) {
#pragma unroll
                    for (int nt = 0; nt < 4; ++nt)
#pragma unroll
                        for (int e = 0; e < 4; ++e) ef[0][nt][e] = 0.f;
                    continue;
                }
#pragma unroll
                for (int nt = 0; nt < 4; ++nt)
#pragma unroll
                    for (int e = 0; e < 4; ++e) {
                        int r  = rb[mt] + grp + ((e >= 2) ? 8 : 0);
                        int sg = s0 + nt * 8 + 2 * tig + (e & 1);
                        ef[mt][nt][e] = (sg <= r) ? __expf(ef[mt][nt][e]) : 0.f;
                    }
            }
            // per-column partial sums over this warp's 32 rows
#pragma unroll
            for (int nt = 0; nt < 4; ++nt)
#pragma unroll
                for (int bb2 = 0; bb2 < 2; ++bb2) {
                    float s = ef[0][nt][bb2] + ef[0][nt][bb2 + 2]
                            + ef[1][nt][bb2] + ef[1][nt][bb2 + 2];
                    s += __shfl_xor_sync(0xffffffffu, s, 4);
                    s += __shfl_xor_sync(0xffffffffu, s, 8);
                    s += __shfl_xor_sync(0xffffffffu, s, 16);
                    ps[nt][bb2] = s;
                }
        }
        if (grp == 0) {
#pragma unroll
            for (int nt = 0; nt < 4; ++nt) {
                psumP[warp * 32 + nt * 8 + 2 * tig]     = ps[nt][0];
                psumP[warp * 32 + nt * 8 + 2 * tig + 1] = ps[nt][1];
            }
        }
        __syncthreads();   // single barrier per block (parity buffer handles WAR)

        // every warp reduces its own rinv: lane L -> 1/denom of column s0+L
        float rv;
        {
            float tot = 0.f;
#pragma unroll
            for (int w = 0; w < 8; ++w) tot += psumP[w * 32 + lane];
            rv = 1.0f / tot;
        }

        if (anyact) {
            // PV in bf16 3-term, k16 (C-frag == A-frag layout, no P shuffles)
#pragma unroll
            for (int ch = 0; ch < 2; ++ch) {
                const int sb = s0 + ch * 16;
                unsigned pah[2][4], pal[2][4];
#pragma unroll
                for (int mt = 0; mt < 2; ++mt) {
                    if (mt == 0 && !act0) continue;
#pragma unroll
                    for (int hq = 0; hq < 2; ++hq) {
                        float e0 = ef[mt][2 * ch + hq][0];
                        float e1 = ef[mt][2 * ch + hq][1];
                        float e2 = ef[mt][2 * ch + hq][2];
                        float e3 = ef[mt][2 * ch + hq][3];
                        pah[mt][2 * hq]     = pk2(e0, e1);
                        pal[mt][2 * hq]     = pkres(e0, e1, pah[mt][2 * hq]);
                        pah[mt][2 * hq + 1] = pk2(e2, e3);
                        pal[mt][2 * hq + 1] = pkres(e2, e3, pah[mt][2 * hq + 1]);
                    }
                }
                float r0 = __shfl_sync(0xffffffffu, rv, ch * 16 + 2 * tig);
                float r1 = __shfl_sync(0xffffffffu, rv, ch * 16 + 2 * tig + 1);
                float r2 = __shfl_sync(0xffffffffu, rv, ch * 16 + 8 + 2 * tig);
                float r3 = __shfl_sync(0xffffffffu, rv, ch * 16 + 9 + 2 * tig);
#pragma unroll
                for (int nt = 0; nt < 2; ++nt) {
                    int d = nt * 8 + grp;
                    float b0 = v_s[(sb + 2 * tig)     * VPD + d] * r0;
                    float b1 = v_s[(sb + 2 * tig + 1) * VPD + d] * r1;
                    float b2 = v_s[(sb + 8 + 2 * tig) * VPD + d] * r2;
                    float b3 = v_s[(sb + 9 + 2 * tig) * VPD + d] * r3;
                    unsigned bh[2], bl[2];
                    bh[0] = pk2(b0, b1); bl[0] = pkres(b0, b1, bh[0]);
                    bh[1] = pk2(b2, b3); bl[1] = pkres(b2, b3, bh[1]);
                    if (act0) {
                        mma_bf16(oacc[0][nt], pah[0], bh);
                        mma_bf16(oacc[0][nt], pah[0], bl);
                        mma_bf16(oacc[0][nt], pal[0], bh);
                    }
                    mma_bf16(oacc[1][nt], pah[1], bh);
                    mma_bf16(oacc[1][nt], pah[1], bl);
                    mma_bf16(oacc[1][nt], pal[1], bh);
                }
            }
        }
    }

    float* ob = out + (size_t)b * TT * HSZ;
#pragma unroll
    for (int mt = 0; mt < 2; ++mt)
#pragma unroll
        for (int nt = 0; nt < 2; ++nt) {
            int r0 = rb[mt] + grp;
            int c  = nt * 8 + 2 * tig;
            *reinterpret_cast<float2*>(ob + r0 * HSZ + c) =
                make_float2(oacc[mt][nt][0], oacc[mt][nt][1]);
            *reinterpret_cast<float2*>(ob + (r0 + 8) * HSZ + c) =
                make_float2(oacc[mt][nt][2], oacc[mt][nt][3]);
        }
}

extern "C" void kernel_launch(void* const* d_in, const int* in_sizes, int n_in,
                              void* d_out, int out_size) {
    const float* x  = (const float*)d_in[0];
    const float* wk = (const float*)d_in[1];
    const float* wq = (const float*)d_in[2];
    const float* wv = (const float*)d_in[3];
    float* out      = (float*)d_out;

    const int B = in_sizes[0] / (TT * CC);  // 512

    cudaFuncSetAttribute(head_fused_kernel,
                         cudaFuncAttributeMaxDynamicSharedMemorySize, SMEM_BYTES);

    pack_w_kernel<<<18, 256>>>(wk, wq, wv);
    head_fused_kernel<<<B, 256, SMEM_BYTES>>>(x, out);
}